// round 15
// baseline (speedup 1.0000x reference)
#include <cuda_runtime.h>
#include <cstdint>

// field[i,j] = sum_n w_n * ox_n[i] * oy_n[j] / (lx*ly)
// dims < 3/G per axis -> footprint <= 4x4 cells.
// R14: PDL refined. Zero kernel releases dependents EARLY
//      (griddepcontrol.launch_dependents right after its store). Scatter body
//      is the exact R9 code with one griddepcontrol.wait immediately before
//      the RED block (everything before it is independent of `field`).
// 1 thread per rect; cell-unit coords; aligned-quad red.global.add.v4.f32.

#define G 256

__global__ void zero_field_kernel4(float4* __restrict__ out, int n4) {
    int i = blockIdx.x * blockDim.x + threadIdx.x;
    if (i < n4) out[i] = make_float4(0.f, 0.f, 0.f, 0.f);
    // Release dependent grid as soon as our stores are issued.
    asm volatile("griddepcontrol.launch_dependents;");
}

__device__ __forceinline__ void red_v4(float* addr, float v0, float v1, float v2, float v3) {
    asm volatile("red.global.add.v4.f32 [%0], {%1, %2, %3, %4};"
                 :: "l"(addr), "f"(v0), "f"(v1), "f"(v2), "f"(v3) : "memory");
}

__global__ void __launch_bounds__(256) charge_scatter_kernel(
    const float4* __restrict__ boundary,  // [xmin, ymin, xmax, ymax]
    const float2* __restrict__ xy,        // [N]
    const float2* __restrict__ dims,      // [N]
    const float* __restrict__ cw,         // [N]
    float* __restrict__ field,            // [G*G]
    int n)
{
    int r = blockIdx.x * blockDim.x + threadIdx.x;
    if (r >= n) {
        asm volatile("griddepcontrol.wait;");
        return;
    }

    // ---- Phase 1: independent of `field` (overlaps the zero-fill) ----
    const float2 p = xy[r];
    const float2 d = dims[r];
    const float w = cw[r];

    const float4 b = *boundary;
    const float inv_lx = __frcp_rn((b.z - b.x) * (1.0f / G));  // exact: lx = 2^-8
    const float inv_ly = __frcp_rn((b.w - b.y) * (1.0f / G));

    const float x0u = (p.x - b.x) * inv_lx;
    const float x1u = (p.x + d.x - b.x) * inv_lx;
    const float y0u = (p.y - b.y) * inv_ly;
    const float y1u = (p.y + d.y - b.y) * inv_ly;

    const int i0 = max((int)floorf(x0u), 0);
    const int j0 = max((int)floorf(y0u), 0);
    const int jq0 = j0 & ~3;              // aligned quad base, <= 252: in-grid
    const int jq1 = jq0 + 4;

    float q0[4], q1[4];
    #pragma unroll
    for (int k = 0; k < 4; k++) {
        float c = (float)(jq0 + k);
        q0[k] = fmaxf(fminf(y1u, c + 1.0f) - fmaxf(y0u, c), 0.0f);
    }
    const bool use1 = (jq1 < G) && (y1u > (float)jq1);
    #pragma unroll
    for (int k = 0; k < 4; k++) {
        float c = (float)(jq1 + k);
        q1[k] = fmaxf(fminf(y1u, c + 1.0f) - fmaxf(y0u, c), 0.0f);
    }

    // ---- Wait for zero-fill visibility, then fire-and-forget REDs ----
    asm volatile("griddepcontrol.wait;");

    #pragma unroll
    for (int s = 0; s < 4; s++) {
        int i = i0 + s;
        float fi = (float)i;
        float oxu = fmaxf(fminf(x1u, fi + 1.0f) - fmaxf(x0u, fi), 0.0f);
        float sx = w * oxu;
        if (i < G && sx != 0.0f) {
            float* rowbase = field + i * G;
            red_v4(rowbase + jq0, sx * q0[0], sx * q0[1], sx * q0[2], sx * q0[3]);
            if (use1) red_v4(rowbase + jq1, sx * q1[0], sx * q1[1], sx * q1[2], sx * q1[3]);
        }
    }
}

extern "C" void kernel_launch(void* const* d_in, const int* in_sizes, int n_in,
                              void* d_out, int out_size) {
    const float4* boundary = (const float4*)d_in[0];
    const float2* xy       = (const float2*)d_in[1];
    const float2* dims     = (const float2*)d_in[2];
    const float*  cw       = (const float*)d_in[3];
    float* field = (float*)d_out;

    const int n = in_sizes[3];          // N_RECTS

    int n4 = out_size / 4;
    zero_field_kernel4<<<(n4 + 255) / 256, 256>>>((float4*)field, n4);

    // Scatter with PDL: begins while zero-fill drains; REDs gated by
    // griddepcontrol.wait.
    cudaLaunchAttribute attrs[1];
    attrs[0].id = cudaLaunchAttributeProgrammaticStreamSerialization;
    attrs[0].val.programmaticStreamSerializationAllowed = 1;

    cudaLaunchConfig_t cfg = {};
    cfg.gridDim  = dim3((n + 255) / 256, 1, 1);
    cfg.blockDim = dim3(256, 1, 1);
    cfg.dynamicSmemBytes = 0;
    cfg.stream = 0;
    cfg.attrs = attrs;
    cfg.numAttrs = 1;

    cudaLaunchKernelEx(&cfg, charge_scatter_kernel,
                       boundary, xy, dims, cw, field, n);
}